// round 2
// baseline (speedup 1.0000x reference)
#include <cuda_runtime.h>

#define NN 50000
#define EE 800000
#define HH 128
#define DD 3
#define TE 32
#define TN 32
#define SP 36   // padded edge-dim stride (floats); 36*4=144B, 16B aligned rows

typedef unsigned long long u64;
union F2 { u64 u; float f[2]; float2 v; };

// ---------------- device scratch ----------------
__device__ float g_agg[NN * HH];
__device__ float g_coord[NN * DD];
__device__ float g_cnt[NN];

__device__ __forceinline__ float silu_f(float v) { return v / (1.0f + __expf(-v)); }
__device__ __forceinline__ float sigmoid_f(float v) { return 1.0f / (1.0f + __expf(-v)); }

// packed fp32x2 helpers (Blackwell f32x2 pipe: 2 MACs per FFMA2 inst)
__device__ __forceinline__ u64 pack_dup(float w) {
    u64 r; asm("mov.b64 %0, {%1, %1};" : "=l"(r) : "f"(w)); return r;
}
__device__ __forceinline__ void ffma2(u64& d, u64 a, u64 b) {
    asm("fma.rn.f32x2 %0, %1, %2, %0;" : "+l"(d) : "l"(a), "l"(b));
}

__global__ void zero_kernel() {
    const int total = NN * HH + NN * DD + NN;
    for (int i = blockIdx.x * blockDim.x + threadIdx.x; i < total;
         i += gridDim.x * blockDim.x) {
        if (i < NN * HH) g_agg[i] = 0.0f;
        else if (i < NN * HH + NN * DD) g_coord[i - NN * HH] = 0.0f;
        else g_cnt[i - NN * HH - NN * DD] = 0.0f;
    }
}

// GEMV over K rows of [k][edge-pair] shared input, packed f32x2 accumulation.
// Thread owns output feature `tid`; acc[p] accumulates edges (2p, 2p+1).
__device__ __forceinline__ void gemv2(const float* __restrict__ W,
                                      const float* sIn, int tid, u64 acc[16], int K) {
    #pragma unroll
    for (int p = 0; p < 16; ++p) acc[p] = 0ull;
    for (int k0 = 0; k0 < K; k0 += 4) {
        const u64 w0 = pack_dup(W[(k0 + 0) * HH + tid]);
        const u64 w1 = pack_dup(W[(k0 + 1) * HH + tid]);
        const u64 w2 = pack_dup(W[(k0 + 2) * HH + tid]);
        const u64 w3 = pack_dup(W[(k0 + 3) * HH + tid]);
        const float2* r0 = (const float2*)(sIn + (k0 + 0) * SP);
        const float2* r1 = (const float2*)(sIn + (k0 + 1) * SP);
        const float2* r2 = (const float2*)(sIn + (k0 + 2) * SP);
        const float2* r3 = (const float2*)(sIn + (k0 + 3) * SP);
        #pragma unroll
        for (int p = 0; p < 16; ++p) {
            F2 v0; v0.v = r0[p]; ffma2(acc[p], v0.u, w0);
            F2 v1; v1.v = r1[p]; ffma2(acc[p], v1.u, w1);
            F2 v2; v2.v = r2[p]; ffma2(acc[p], v2.u, w2);
            F2 v3; v3.v = r3[p]; ffma2(acc[p], v3.u, w3);
        }
    }
}

// ---------------- fused edge kernel ----------------
__global__ __launch_bounds__(128) void edge_kernel(
    const float* __restrict__ h, const float* __restrict__ x,
    const int* __restrict__ ei, const float* __restrict__ eattr,
    const float* __restrict__ EW1, const float* __restrict__ eb1,
    const float* __restrict__ EW2, const float* __restrict__ eb2,
    const float* __restrict__ CW1, const float* __restrict__ cb1,
    const float* __restrict__ CW2, const float* __restrict__ AW,
    const float* __restrict__ ab)
{
    // [k][e] layout, stride SP. s_in rows 0..259 (258 used).
    // Aliased: s_h = rows 0..127, s_m = rows 128..255.
    __shared__ float sbuf[260 * SP];      // 9360 floats = 37.4 KB
    __shared__ int   s_row[TE];
    __shared__ float s_cd[TE][3];
    __shared__ float s_att[TE];
    __shared__ float s_red[4][TE];

    float* s_in = sbuf;
    float* s_h  = sbuf;                 // floats [0, 4608)
    float* s_m  = sbuf + 128 * SP;      // floats [4608, 9216)

    const int tid = threadIdx.x;
    const int e0  = blockIdx.x * TE;

    // ---- gather ----
    #pragma unroll 4
    for (int e = 0; e < TE; ++e) {
        int idx = e0 + e; if (idx >= EE) idx = EE - 1;
        const int r = ei[idx];
        const int c = ei[EE + idx];
        s_in[tid * SP + e]         = h[r * HH + tid];   // h[row] -> rows 0..127
        s_in[(128 + tid) * SP + e] = h[c * HH + tid];   // h[col] -> rows 128..255
    }
    if (tid < TE) {
        int idx = e0 + tid; if (idx >= EE) idx = EE - 1;
        const int r = ei[idx];
        const int c = ei[EE + idx];
        s_row[tid] = r;
        float rad = 0.0f;
        #pragma unroll
        for (int d = 0; d < 3; ++d) {
            const float df = x[r * 3 + d] - x[c * 3 + d];
            s_cd[tid][d] = df;
            rad += df * df;
        }
        s_in[256 * SP + tid] = rad;
        s_in[257 * SP + tid] = eattr[idx];
    }
    __syncthreads();

    u64 acc[16];

    // ---- layer 1: K = 256 main + 2 tail rows ----
    gemv2(EW1, s_in, tid, acc, 256);
    {
        const u64 wr = pack_dup(EW1[256 * HH + tid]);
        const u64 we = pack_dup(EW1[257 * HH + tid]);
        const float2* rr = (const float2*)(s_in + 256 * SP);
        const float2* re = (const float2*)(s_in + 257 * SP);
        #pragma unroll
        for (int p = 0; p < 16; ++p) {
            F2 v0; v0.v = rr[p]; ffma2(acc[p], v0.u, wr);
            F2 v1; v1.v = re[p]; ffma2(acc[p], v1.u, we);
        }
    }
    const float bb1 = eb1[tid];
    __syncthreads();   // all s_in reads done before aliased s_h write
    #pragma unroll
    for (int p = 0; p < 16; ++p) {
        F2 a; a.u = acc[p];
        s_h[tid * SP + 2 * p]     = silu_f(a.f[0] + bb1);
        s_h[tid * SP + 2 * p + 1] = silu_f(a.f[1] + bb1);
    }
    __syncthreads();

    // ---- layer 2: K = 128 ----
    gemv2(EW2, s_h, tid, acc, 128);
    const float bb2 = eb2[tid];
    #pragma unroll
    for (int p = 0; p < 16; ++p) {
        F2 a; a.u = acc[p];
        s_m[tid * SP + 2 * p]     = silu_f(a.f[0] + bb2);
        s_m[tid * SP + 2 * p + 1] = silu_f(a.f[1] + bb2);
    }
    __syncthreads();

    // ---- attention gate ----
    {
        const int e = tid & 31, q = tid >> 5;
        float s = 0.0f;
        #pragma unroll
        for (int kk = 0; kk < 32; ++kk) {
            const int k = q * 32 + kk;
            s += s_m[k * SP + e] * AW[k];
        }
        s_red[q][e] = s;
    }
    __syncthreads();
    if (tid < TE) {
        const float s = s_red[0][tid] + s_red[1][tid] + s_red[2][tid] + s_red[3][tid] + ab[0];
        s_att[tid] = sigmoid_f(s);
    }
    __syncthreads();
    #pragma unroll
    for (int e = 0; e < TE; ++e) s_m[tid * SP + e] *= s_att[e];
    __syncthreads();

    // ---- scatter gated messages ----
    #pragma unroll
    for (int e = 0; e < TE; ++e) {
        if (e0 + e < EE)
            atomicAdd(&g_agg[s_row[e] * HH + tid], s_m[tid * SP + e]);
    }

    // ---- coord MLP layer 1 ----
    gemv2(CW1, s_m, tid, acc, 128);
    const float bbc = cb1[tid];
    #pragma unroll
    for (int p = 0; p < 16; ++p) {
        F2 a; a.u = acc[p];
        s_h[tid * SP + 2 * p]     = silu_f(a.f[0] + bbc);
        s_h[tid * SP + 2 * p + 1] = silu_f(a.f[1] + bbc);
    }
    __syncthreads();

    // ---- coord_update = p @ c_w2 ; scatter ----
    {
        const int e = tid & 31, q = tid >> 5;
        float s = 0.0f;
        #pragma unroll
        for (int kk = 0; kk < 32; ++kk) {
            const int k = q * 32 + kk;
            s += s_h[k * SP + e] * CW2[k];
        }
        s_red[q][e] = s;
    }
    __syncthreads();
    if (tid < TE && e0 + tid < EE) {
        const float cu = s_red[0][tid] + s_red[1][tid] + s_red[2][tid] + s_red[3][tid];
        const int r = s_row[tid];
        atomicAdd(&g_coord[r * 3 + 0], s_cd[tid][0] * cu);
        atomicAdd(&g_coord[r * 3 + 1], s_cd[tid][1] * cu);
        atomicAdd(&g_coord[r * 3 + 2], s_cd[tid][2] * cu);
        atomicAdd(&g_cnt[r], 1.0f);
    }
}

// ---------------- node update kernel ----------------
__global__ __launch_bounds__(128) void node_kernel(
    const float* __restrict__ h, const float* __restrict__ x,
    const float* __restrict__ NW1, const float* __restrict__ nb1,
    const float* __restrict__ NW2, const float* __restrict__ nb2,
    float* __restrict__ out_h, float* __restrict__ out_x)
{
    __shared__ float sbuf[256 * SP];   // 9216 floats
    float* s_in = sbuf;                // rows 0..255
    float* s_t  = sbuf;                // rows 0..127 (alias)

    const int tid = threadIdx.x;
    const int n0  = blockIdx.x * TN;

    #pragma unroll 4
    for (int n = 0; n < TN; ++n) {
        int r = n0 + n; if (r >= NN) r = NN - 1;
        s_in[tid * SP + n]         = h[r * HH + tid];
        s_in[(128 + tid) * SP + n] = g_agg[r * HH + tid];
    }
    __syncthreads();

    u64 acc[16];
    gemv2(NW1, s_in, tid, acc, 256);
    const float bb1 = nb1[tid];
    __syncthreads();
    #pragma unroll
    for (int p = 0; p < 16; ++p) {
        F2 a; a.u = acc[p];
        s_t[tid * SP + 2 * p]     = silu_f(a.f[0] + bb1);
        s_t[tid * SP + 2 * p + 1] = silu_f(a.f[1] + bb1);
    }
    __syncthreads();

    gemv2(NW2, s_t, tid, acc, 128);
    const float bb2 = nb2[tid];
    #pragma unroll
    for (int p = 0; p < 16; ++p) {
        F2 a; a.u = acc[p];
        const int r0 = n0 + 2 * p;
        if (r0 < NN)     out_h[r0 * HH + tid]       = h[r0 * HH + tid] + a.f[0] + bb2;
        if (r0 + 1 < NN) out_h[(r0 + 1) * HH + tid] = h[(r0 + 1) * HH + tid] + a.f[1] + bb2;
    }

    if (tid < TN * DD) {
        const int n = tid / 3, d = tid % 3;
        const int r = n0 + n;
        if (r < NN) {
            float cnt = g_cnt[r];
            cnt = (cnt < 1.0f) ? 1.0f : cnt;
            out_x[r * 3 + d] = x[r * 3 + d] + g_coord[r * 3 + d] / cnt;
        }
    }
}

// ---------------- launch ----------------
extern "C" void kernel_launch(void* const* d_in, const int* in_sizes, int n_in,
                              void* d_out, int out_size) {
    const float* h     = (const float*)d_in[0];
    const float* x     = (const float*)d_in[1];
    const int*   ei    = (const int*)d_in[2];
    const float* eattr = (const float*)d_in[3];
    const float* EW1   = (const float*)d_in[4];
    const float* eb1   = (const float*)d_in[5];
    const float* EW2   = (const float*)d_in[6];
    const float* eb2   = (const float*)d_in[7];
    const float* NW1   = (const float*)d_in[8];
    const float* nb1   = (const float*)d_in[9];
    const float* NW2   = (const float*)d_in[10];
    const float* nb2   = (const float*)d_in[11];
    const float* CW1   = (const float*)d_in[12];
    const float* cb1   = (const float*)d_in[13];
    const float* CW2   = (const float*)d_in[14];
    const float* AW    = (const float*)d_in[15];
    const float* ab    = (const float*)d_in[16];

    float* out_h = (float*)d_out;
    float* out_x = (float*)d_out + (size_t)NN * HH;

    zero_kernel<<<1024, 256>>>();
    edge_kernel<<<(EE + TE - 1) / TE, 128>>>(h, x, ei, eattr,
                                             EW1, eb1, EW2, eb2,
                                             CW1, cb1, CW2, AW, ab);
    node_kernel<<<(NN + TN - 1) / TN, 128>>>(h, x, NW1, nb1, NW2, nb2,
                                             out_h, out_x);
}

// round 3
// speedup vs baseline: 2.1515x; 2.1515x over previous
#include <cuda_runtime.h>

#define NN 50000
#define EE 800000
#define HH 128
#define DD 3
#define EM 64      // edges per block
#define KC 64      // K tile rows
#define WS 136     // W_s stride (floats), 136%32=8 -> conflict-free B frags
#define SA 268     // A1 stride (K padded to 264), 268%32=4 -> conflict-free A frags
#define S2 132     // A2/M/P stride, 132%32=4
#define TN 32

// ---------------- device scratch ----------------
__device__ float g_agg[NN * HH];
__device__ float g_coord[NN * DD];
__device__ float g_cnt[NN];

__device__ __forceinline__ float silu_f(float v) { return v / (1.0f + __expf(-v)); }
__device__ __forceinline__ float sigmoid_f(float v) { return 1.0f / (1.0f + __expf(-v)); }
__device__ __forceinline__ float tf32r(float v) {
    unsigned r; asm("cvt.rna.tf32.f32 %0, %1;" : "=r"(r) : "f"(v));
    return __uint_as_float(r);
}
__device__ __forceinline__ void mma_tf32(float c[4],
    unsigned a0, unsigned a1, unsigned a2, unsigned a3,
    unsigned b0, unsigned b1)
{
    asm volatile("mma.sync.aligned.m16n8k8.row.col.f32.tf32.tf32.f32 "
        "{%0,%1,%2,%3}, {%4,%5,%6,%7}, {%8,%9}, {%0,%1,%2,%3};\n"
        : "+f"(c[0]), "+f"(c[1]), "+f"(c[2]), "+f"(c[3])
        : "r"(a0), "r"(a1), "r"(a2), "r"(a3), "r"(b0), "r"(b1));
}

__global__ void zero_kernel() {
    const int total = NN * HH + NN * DD + NN;
    for (int i = blockIdx.x * blockDim.x + threadIdx.x; i < total;
         i += gridDim.x * blockDim.x) {
        if (i < NN * HH) g_agg[i] = 0.0f;
        else if (i < NN * HH + NN * DD) g_coord[i - NN * HH] = 0.0f;
        else g_cnt[i - NN * HH - NN * DD] = 0.0f;
    }
}

// GEMM: acc[8][4] += A[warp rows, 0:Ktot] @ W[0:Ktot, warp cols]
// W loaded from global in KC-row tiles into Wt (zero-padded past Kreal, tf32-rounded).
// A already tf32-rounded in smem. Starts with __syncthreads() (covers caller's smem writes).
__device__ __forceinline__ void gemm_tile(
    const float* __restrict__ Wg, int Kreal, int Ktot,
    const float* As, int sa, float* Wt,
    float acc[8][4], int tid, int wm, int wn, int g, int t)
{
    for (int k0 = 0; k0 < Ktot; k0 += KC) {
        const int kc = (Ktot - k0 < KC) ? (Ktot - k0) : KC;
        __syncthreads();
        for (int i = tid; i < kc * 32; i += 256) {
            const int kr = i >> 5, c4 = (i & 31) << 2;
            const int kg = k0 + kr;
            float4 v = make_float4(0.f, 0.f, 0.f, 0.f);
            if (kg < Kreal) v = *(const float4*)&Wg[kg * HH + c4];
            v.x = tf32r(v.x); v.y = tf32r(v.y); v.z = tf32r(v.z); v.w = tf32r(v.w);
            *(float4*)&Wt[kr * WS + c4] = v;
        }
        __syncthreads();
        const int nch = kc >> 3;
        const float* arow = As + (wm * 16 + g) * sa + t;
        for (int kk = 0; kk < nch; ++kk) {
            const int ka = k0 + kk * 8;
            const unsigned a0 = __float_as_uint(arow[ka]);
            const unsigned a1 = __float_as_uint(arow[8 * sa + ka]);
            const unsigned a2 = __float_as_uint(arow[ka + 4]);
            const unsigned a3 = __float_as_uint(arow[8 * sa + ka + 4]);
            const float* wb = Wt + kk * 8 * WS + wn * 64 + g;
            #pragma unroll
            for (int n8 = 0; n8 < 8; ++n8) {
                const unsigned b0 = __float_as_uint(wb[t * WS + n8 * 8]);
                const unsigned b1 = __float_as_uint(wb[(t + 4) * WS + n8 * 8]);
                mma_tf32(acc[n8], a0, a1, a2, a3, b0, b1);
            }
        }
    }
}

__device__ __forceinline__ void acc_zero(float acc[8][4]) {
    #pragma unroll
    for (int i = 0; i < 8; ++i)
        #pragma unroll
        for (int j = 0; j < 4; ++j) acc[i][j] = 0.f;
}

// epilogue: silu(acc + bias[col]) -> tf32-rounded -> Out (stride s)
__device__ __forceinline__ void epi_silu_store(
    float acc[8][4], float* Out, int s, const float* bias,
    int wm, int wn, int g, int t)
{
    const int r0 = wm * 16 + g;
    #pragma unroll
    for (int n8 = 0; n8 < 8; ++n8) {
        const int c = wn * 64 + n8 * 8 + 2 * t;
        const float b0 = bias[c], b1 = bias[c + 1];
        float2 lo, hi;
        lo.x = tf32r(silu_f(acc[n8][0] + b0));
        lo.y = tf32r(silu_f(acc[n8][1] + b1));
        hi.x = tf32r(silu_f(acc[n8][2] + b0));
        hi.y = tf32r(silu_f(acc[n8][3] + b1));
        *(float2*)&Out[r0 * s + c]       = lo;
        *(float2*)&Out[(r0 + 8) * s + c] = hi;
    }
}

// ---------------- fused edge kernel (tensor-core) ----------------
__global__ __launch_bounds__(256, 2) void edge_kernel(
    const float* __restrict__ h, const float* __restrict__ x,
    const int* __restrict__ ei, const float* __restrict__ eattr,
    const float* __restrict__ EW1, const float* __restrict__ eb1,
    const float* __restrict__ EW2, const float* __restrict__ eb2,
    const float* __restrict__ CW1, const float* __restrict__ cb1,
    const float* __restrict__ CW2, const float* __restrict__ AW,
    const float* __restrict__ ab)
{
    extern __shared__ float dsm[];
    float* A1 = dsm;               // [64][268]  (layer-1 input, K-padded)
    float* A2 = dsm;               // [64][132]  alias (dead A1 after layer 1)
    float* Mm = dsm + EM * S2;     // [64][132]  gated messages
    float* Wt = dsm + EM * SA;     // [64][136]  weight tile

    __shared__ int   s_row[EM];
    __shared__ float s_cd[EM][3];
    __shared__ float s_att[EM];
    __shared__ float s_b1[HH], s_b2[HH], s_bc[HH], s_aw[HH], s_c2[HH];

    const int tid  = threadIdx.x;
    const int lane = tid & 31, warp = tid >> 5;
    const int g = lane >> 2, t = lane & 3;
    const int wm = warp & 3, wn = warp >> 2;
    const int e0 = blockIdx.x * EM;

    // preload bias/small vectors
    if (tid < HH) {
        s_b1[tid] = eb1[tid]; s_b2[tid] = eb2[tid]; s_bc[tid] = cb1[tid];
        s_aw[tid] = AW[tid];  s_c2[tid] = CW2[tid];
    }
    // geometry, indices, radial/eattr, zero K-pad
    if (tid >= 128 && tid < 128 + EM) {
        const int e = tid - 128;
        const int idx = e0 + e;
        const int r = ei[idx], c = ei[EE + idx];
        s_row[e] = r;
        float rad = 0.f;
        #pragma unroll
        for (int d = 0; d < 3; ++d) {
            const float df = x[r * 3 + d] - x[c * 3 + d];
            s_cd[e][d] = df; rad += df * df;
        }
        A1[e * SA + 256] = tf32r(rad);
        A1[e * SA + 257] = tf32r(eattr[idx]);
        #pragma unroll
        for (int k = 258; k < 264; ++k) A1[e * SA + k] = 0.f;
    }
    // gather h[row], h[col] (warp w handles edges w, w+8, ..., coalesced float4)
    {
        const int c4 = lane * 4;
        #pragma unroll
        for (int p = 0; p < 8; ++p) {
            const int e = p * 8 + warp;
            const int idx = e0 + e;
            const int r = ei[idx], c = ei[EE + idx];
            float4 vr = *(const float4*)&h[r * HH + c4];
            float4 vc = *(const float4*)&h[c * HH + c4];
            vr.x = tf32r(vr.x); vr.y = tf32r(vr.y); vr.z = tf32r(vr.z); vr.w = tf32r(vr.w);
            vc.x = tf32r(vc.x); vc.y = tf32r(vc.y); vc.z = tf32r(vc.z); vc.w = tf32r(vc.w);
            *(float4*)&A1[e * SA + c4]       = vr;
            *(float4*)&A1[e * SA + 128 + c4] = vc;
        }
    }
    // (gemm_tile begins with __syncthreads(): covers all writes above)

    float acc[8][4];

    // ---- layer 1: [64,264] @ [264->258,128] ----
    acc_zero(acc);
    gemm_tile(EW1, 258, 264, A1, SA, Wt, acc, tid, wm, wn, g, t);
    __syncthreads();                       // all A1 reads complete before alias write
    epi_silu_store(acc, A2, S2, s_b1, wm, wn, g, t);

    // ---- layer 2: [64,128] @ [128,128] ----
    acc_zero(acc);
    gemm_tile(EW2, 128, 128, A2, S2, Wt, acc, tid, wm, wn, g, t);
    __syncthreads();
    epi_silu_store(acc, Mm, S2, s_b2, wm, wn, g, t);
    __syncthreads();

    // ---- attention gate: 4 threads per edge ----
    {
        const int e = tid >> 2, q = tid & 3;
        float s = 0.f;
        const float* mrow = Mm + e * S2 + q * 32;
        const float* aw   = s_aw + q * 32;
        #pragma unroll
        for (int kk = 0; kk < 32; ++kk) s += mrow[kk] * aw[kk];
        s += __shfl_down_sync(0xffffffffu, s, 1);
        s += __shfl_down_sync(0xffffffffu, s, 2);
        if (q == 0) s_att[e] = sigmoid_f(s + ab[0]);
    }
    __syncthreads();
    // scale m by att (keep tf32-rounded: it's layer-3's A operand)
    #pragma unroll
    for (int p = 0; p < 32; ++p) {
        const int idx = p * 256 + tid;
        const int e = idx >> 7, f = idx & 127;
        Mm[e * S2 + f] = tf32r(Mm[e * S2 + f] * s_att[e]);
    }
    __syncthreads();
    // ---- scatter gated messages ----
    #pragma unroll
    for (int p = 0; p < 32; ++p) {
        const int idx = p * 256 + tid;
        const int e = idx >> 7, f = idx & 127;
        atomicAdd(&g_agg[s_row[e] * HH + f], Mm[e * S2 + f]);
    }

    // ---- coord MLP layer: [64,128] @ [128,128] ----
    acc_zero(acc);
    gemm_tile(CW1, 128, 128, Mm, S2, Wt, acc, tid, wm, wn, g, t);
    __syncthreads();
    epi_silu_store(acc, A2, S2, s_bc, wm, wn, g, t);   // P -> A2 region (dead)
    __syncthreads();

    // ---- coord_update = P @ c_w2 ; scatter coords + counts ----
    {
        const int e = tid >> 2, q = tid & 3;
        float s = 0.f;
        const float* prow = A2 + e * S2 + q * 32;
        const float* c2   = s_c2 + q * 32;
        #pragma unroll
        for (int kk = 0; kk < 32; ++kk) s += prow[kk] * c2[kk];
        s += __shfl_down_sync(0xffffffffu, s, 1);
        s += __shfl_down_sync(0xffffffffu, s, 2);
        if (q == 0) {
            const int r = s_row[e];
            atomicAdd(&g_coord[r * 3 + 0], s_cd[e][0] * s);
            atomicAdd(&g_coord[r * 3 + 1], s_cd[e][1] * s);
            atomicAdd(&g_coord[r * 3 + 2], s_cd[e][2] * s);
            atomicAdd(&g_cnt[r], 1.0f);
        }
    }
}

// ---------------- node update kernel (round-1 proven version) ----------------
__global__ __launch_bounds__(128) void node_kernel(
    const float* __restrict__ h, const float* __restrict__ x,
    const float* __restrict__ NW1, const float* __restrict__ nb1,
    const float* __restrict__ NW2, const float* __restrict__ nb2,
    float* __restrict__ out_h, float* __restrict__ out_x)
{
    __shared__ float sbuf[8192];
    float* s_in = sbuf;
    float* s_t  = sbuf;

    const int tid = threadIdx.x;
    const int n0  = blockIdx.x * TN;

    #pragma unroll 4
    for (int n = 0; n < TN; ++n) {
        int r = n0 + n; if (r >= NN) r = NN - 1;
        s_in[n * 256 + tid]       = h[r * HH + tid];
        s_in[n * 256 + 128 + tid] = g_agg[r * HH + tid];
    }
    __syncthreads();

    float acc[TN];
    #pragma unroll
    for (int n = 0; n < TN; ++n) acc[n] = 0.0f;
    for (int k4 = 0; k4 < 64; ++k4) {
        const int k = k4 * 4;
        const float w0 = NW1[(k + 0) * HH + tid];
        const float w1 = NW1[(k + 1) * HH + tid];
        const float w2 = NW1[(k + 2) * HH + tid];
        const float w3 = NW1[(k + 3) * HH + tid];
        #pragma unroll
        for (int n = 0; n < TN; ++n) {
            const float4 v = *(const float4*)&s_in[n * 256 + k];
            acc[n] += v.x * w0;
            acc[n] += v.y * w1;
            acc[n] += v.z * w2;
            acc[n] += v.w * w3;
        }
    }
    const float bb1 = nb1[tid];
    __syncthreads();
    #pragma unroll
    for (int n = 0; n < TN; ++n) s_t[n * 132 + tid] = silu_f(acc[n] + bb1);
    __syncthreads();

    #pragma unroll
    for (int n = 0; n < TN; ++n) acc[n] = 0.0f;
    for (int k4 = 0; k4 < 32; ++k4) {
        const int k = k4 * 4;
        const float w0 = NW2[(k + 0) * HH + tid];
        const float w1 = NW2[(k + 1) * HH + tid];
        const float w2 = NW2[(k + 2) * HH + tid];
        const float w3 = NW2[(k + 3) * HH + tid];
        #pragma unroll
        for (int n = 0; n < TN; ++n) {
            const float4 v = *(const float4*)&s_t[n * 132 + k];
            acc[n] += v.x * w0;
            acc[n] += v.y * w1;
            acc[n] += v.z * w2;
            acc[n] += v.w * w3;
        }
    }
    const float bb2 = nb2[tid];
    #pragma unroll
    for (int n = 0; n < TN; ++n) {
        const int r = n0 + n;
        if (r < NN)
            out_h[r * HH + tid] = h[r * HH + tid] + acc[n] + bb2;
    }

    if (tid < TN * DD) {
        const int n = tid / 3, d = tid % 3;
        const int r = n0 + n;
        if (r < NN) {
            float cnt = g_cnt[r];
            cnt = (cnt < 1.0f) ? 1.0f : cnt;
            out_x[r * 3 + d] = x[r * 3 + d] + g_coord[r * 3 + d] / cnt;
        }
    }
}

// ---------------- launch ----------------
extern "C" void kernel_launch(void* const* d_in, const int* in_sizes, int n_in,
                              void* d_out, int out_size) {
    const float* h     = (const float*)d_in[0];
    const float* x     = (const float*)d_in[1];
    const int*   ei    = (const int*)d_in[2];
    const float* eattr = (const float*)d_in[3];
    const float* EW1   = (const float*)d_in[4];
    const float* eb1   = (const float*)d_in[5];
    const float* EW2   = (const float*)d_in[6];
    const float* eb2   = (const float*)d_in[7];
    const float* NW1   = (const float*)d_in[8];
    const float* nb1   = (const float*)d_in[9];
    const float* NW2   = (const float*)d_in[10];
    const float* nb2   = (const float*)d_in[11];
    const float* CW1   = (const float*)d_in[12];
    const float* cb1   = (const float*)d_in[13];
    const float* CW2   = (const float*)d_in[14];
    const float* AW    = (const float*)d_in[15];
    const float* ab    = (const float*)d_in[16];

    float* out_h = (float*)d_out;
    float* out_x = (float*)d_out + (size_t)NN * HH;

    const int smem_bytes = (EM * SA + KC * WS) * 4;   // 103,424 B
    cudaFuncSetAttribute(edge_kernel,
                         cudaFuncAttributeMaxDynamicSharedMemorySize, smem_bytes);

    zero_kernel<<<1024, 256>>>();
    edge_kernel<<<EE / EM, 256, smem_bytes>>>(h, x, ei, eattr,
                                              EW1, eb1, EW2, eb2,
                                              CW1, cb1, CW2, AW, ab);
    node_kernel<<<(NN + TN - 1) / TN, 128>>>(h, x, NW1, nb1, NW2, nb2,
                                             out_h, out_x);
}